// round 14
// baseline (speedup 1.0000x reference)
#include <cuda_runtime.h>
#include <cuda_fp16.h>
#include <cstdint>

#define NBATCH 4
#define NQ 2048
#define NF 16384
#define CDIM 768
#define SCALEF 0.57735026918962576f

// ---- GEMM tiling (fp16 operands, fp32 accum), split-K ----
#define BM 128
#define BN 128
#define BK 32
#define SPLITK 2
#define KPS (NF / SPLITK)            // 8192
#define NCH (KPS / BK)               // 256
#define STAGES 5
#define LDT 40                       // padded row length in halves (80B rows)
#define TILE_HALVES (BM * LDT)
#define STAGE_BYTES (2 * TILE_HALVES * 2)    // 20480
#define GEMM_SMEM (STAGES * STAGE_BYTES)     // 102400

__device__ __align__(16) float4 g_qp[NBATCH * NQ];
__device__ __align__(16) float4 g_kp[NBATCH * NF];
__device__ __align__(16) __half g_p[(size_t)NBATCH * NQ * NF];
__device__ __align__(16) __half g_vt[(size_t)NBATCH * CDIM * NF];
__device__ __align__(16) float g_part[(size_t)SPLITK * NBATCH * NQ * CDIM];
__device__ float g_iden[NBATCH * NQ];

__device__ __forceinline__ uint32_t smem_u32(const void* p) {
    uint32_t a;
    asm("{ .reg .u64 t; cvta.to.shared.u64 t, %1; cvt.u32.u64 %0, t; }" : "=r"(a) : "l"(p));
    return a;
}
__device__ __forceinline__ void cp_async16(uint32_t saddr, const void* gaddr) {
    asm volatile("cp.async.cg.shared.global [%0], [%1], 16;" :: "r"(saddr), "l"(gaddr));
}
#define CP_COMMIT() asm volatile("cp.async.commit_group;" ::: "memory")
#define CP_WAIT()   asm volatile("cp.async.wait_group 2;" ::: "memory")

__device__ __forceinline__ void ldm_x4(uint32_t& r0, uint32_t& r1, uint32_t& r2,
                                       uint32_t& r3, uint32_t a) {
    asm volatile("ldmatrix.sync.aligned.m8n8.x4.shared.b16 {%0,%1,%2,%3}, [%4];"
                 : "=r"(r0), "=r"(r1), "=r"(r2), "=r"(r3) : "r"(a));
}
__device__ __forceinline__ void mma_f16(float* d, const uint32_t* a, const uint32_t* b) {
    asm volatile(
        "mma.sync.aligned.m16n8k16.row.col.f32.f16.f16.f32 "
        "{%0,%1,%2,%3}, {%4,%5,%6,%7}, {%8,%9}, {%0,%1,%2,%3};"
        : "+f"(d[0]), "+f"(d[1]), "+f"(d[2]), "+f"(d[3])
        : "r"(a[0]), "r"(a[1]), "r"(a[2]), "r"(a[3]), "r"(b[0]), "r"(b[1]));
}

// ---- Kernel 1: 3x3 projections + ReLU (q pre-scaled by 1/sqrt(3)) ----
__global__ void proj_kernel(const float* __restrict__ q, const float* __restrict__ k,
                            const float* __restrict__ W1, const float* __restrict__ b1,
                            const float* __restrict__ W2, const float* __restrict__ b2) {
    int i = blockIdx.x * blockDim.x + threadIdx.x;
    const int nq = NBATCH * NQ, nf = NBATCH * NF;
    if (i < nq) {
        float x0 = q[3 * i], x1 = q[3 * i + 1], x2 = q[3 * i + 2];
        float4 o;
        o.x = SCALEF * fmaxf(0.f, fmaf(W1[0], x0, fmaf(W1[1], x1, fmaf(W1[2], x2, b1[0]))));
        o.y = SCALEF * fmaxf(0.f, fmaf(W1[3], x0, fmaf(W1[4], x1, fmaf(W1[5], x2, b1[1]))));
        o.z = SCALEF * fmaxf(0.f, fmaf(W1[6], x0, fmaf(W1[7], x1, fmaf(W1[8], x2, b1[2]))));
        o.w = 0.f;
        g_qp[i] = o;
    } else if (i < nq + nf) {
        int j = i - nq;
        float x0 = k[3 * j], x1 = k[3 * j + 1], x2 = k[3 * j + 2];
        float4 o;
        o.x = fmaxf(0.f, fmaf(W2[0], x0, fmaf(W2[1], x1, fmaf(W2[2], x2, b2[0]))));
        o.y = fmaxf(0.f, fmaf(W2[3], x0, fmaf(W2[4], x1, fmaf(W2[5], x2, b2[1]))));
        o.z = fmaxf(0.f, fmaf(W2[6], x0, fmaf(W2[7], x1, fmaf(W2[8], x2, b2[2]))));
        o.w = 0.f;
        g_kp[j] = o;
    }
}

// ---- Kernel 2: row max, then E = exp(s-m) fp16 (half2 stores), 1/den fp32 ----
__global__ void __launch_bounds__(256) exp_kernel() {
    const int m0 = blockIdx.x * 8, b = blockIdx.y;
    const int tid = threadIdx.x;
    float4 qv[8];
    #pragma unroll
    for (int r = 0; r < 8; ++r) qv[r] = g_qp[b * NQ + m0 + r];
    const float4* __restrict__ kp = g_kp + b * NF;
    __half* __restrict__ pbase = g_p + ((size_t)b * NQ + m0) * NF;

    __shared__ float red[8][256];

    float mx[8];
    #pragma unroll
    for (int r = 0; r < 8; ++r) mx[r] = -1e30f;
    for (int i = tid; i < NF; i += 256) {
        float4 kv = kp[i];
        #pragma unroll
        for (int r = 0; r < 8; ++r)
            mx[r] = fmaxf(mx[r], qv[r].x * kv.x + qv[r].y * kv.y + qv[r].z * kv.z);
    }
    #pragma unroll
    for (int r = 0; r < 8; ++r) red[r][tid] = mx[r];
    __syncthreads();
    #pragma unroll
    for (int s = 128; s > 0; s >>= 1) {
        if (tid < s) {
            #pragma unroll
            for (int r = 0; r < 8; ++r)
                red[r][tid] = fmaxf(red[r][tid], red[r][tid + s]);
        }
        __syncthreads();
    }
    #pragma unroll
    for (int r = 0; r < 8; ++r) mx[r] = red[r][0];
    __syncthreads();

    float part[8];
    #pragma unroll
    for (int r = 0; r < 8; ++r) part[r] = 0.f;
    for (int i = 2 * tid; i < NF; i += 512) {
        float4 kva = kp[i], kvb = kp[i + 1];
        #pragma unroll
        for (int r = 0; r < 8; ++r) {
            float ea = __expf(qv[r].x * kva.x + qv[r].y * kva.y + qv[r].z * kva.z - mx[r]);
            float eb = __expf(qv[r].x * kvb.x + qv[r].y * kvb.y + qv[r].z * kvb.z - mx[r]);
            part[r] += ea + eb;
            *reinterpret_cast<__half2*>(pbase + (size_t)r * NF + i) =
                __floats2half2_rn(ea, eb);
        }
    }
    #pragma unroll
    for (int r = 0; r < 8; ++r) red[r][tid] = part[r];
    __syncthreads();
    #pragma unroll
    for (int s = 128; s > 0; s >>= 1) {
        if (tid < s) {
            #pragma unroll
            for (int r = 0; r < 8; ++r) red[r][tid] += red[r][tid + s];
        }
        __syncthreads();
    }
    if (tid < 8) g_iden[b * NQ + m0 + tid] = 1.f / red[tid][0];
}

// ---- Kernel 3: V transpose to [b][c][k], fp16, half2 stores ----
__global__ void transpose_v(const float* __restrict__ v) {
    __shared__ float tile[32][33];
    const int b = blockIdx.z, k0 = blockIdx.x << 5, c0 = blockIdx.y << 5;
    const int x = threadIdx.x, y = threadIdx.y;
    const float* vb = v + ((size_t)b * NF + k0) * CDIM + c0;
    #pragma unroll
    for (int j = 0; j < 32; j += 8) tile[y + j][x] = vb[(size_t)(y + j) * CDIM + x];
    __syncthreads();
    const int flat = y * 32 + x;
    const int cl = flat >> 4, k2 = (flat & 15) * 2;
    __half* o = g_vt + ((size_t)b * CDIM + c0) * NF + k0;
    #pragma unroll
    for (int p = 0; p < 2; ++p) {
        const int c = cl + p * 16;
        *reinterpret_cast<__half2*>(o + (size_t)c * NF + k2) =
            __floats2half2_rn(tile[k2][c], tile[k2 + 1][c]);
    }
}

// Fragment load/compute macros (arrays indexed by constants under unroll)
#define LDM_FRAGS(As, Bs, ks, af, bf) do {                                      \
    _Pragma("unroll")                                                           \
    for (int ma = 0; ma < 4; ++ma)                                              \
        ldm_x4(af[ma][0], af[ma][1], af[ma][2], af[ma][3],                      \
               (As) + (uint32_t)((warp_m * 64 + ma * 16 + a_row) * LDT +        \
                                 (ks) * 16 + a_kh) * 2);                        \
    _Pragma("unroll")                                                           \
    for (int n8 = 0; n8 < 4; ++n8)                                              \
        ldm_x4(bf[2 * n8][0], bf[2 * n8][1], bf[2 * n8 + 1][0],                 \
               bf[2 * n8 + 1][1],                                               \
               (Bs) + (uint32_t)((warp_n * 64 + n8 * 16 + b_nrow) * LDT +       \
                                 (ks) * 16 + b_kh) * 2);                        \
} while (0)

#define MMA_ALL(af, bf) do {                                                    \
    _Pragma("unroll")                                                           \
    for (int ma = 0; ma < 4; ++ma)                                              \
        _Pragma("unroll")                                                       \
        for (int na = 0; na < 8; ++na) mma_f16(acc[ma][na], af[ma], bf[na]);    \
} while (0)

// ---- Kernel 4: fp16 mma GEMM, rolling cross-chunk fragment double-buffer ----
// Grid (6, 16, NBATCH*SPLITK). 128 threads, warp tile 64x64, STAGES=5.
__global__ void __launch_bounds__(128, 2) gemm_kernel() {
    extern __shared__ __half sm[];
    const uint32_t sbase = smem_u32(sm);
    const int b = blockIdx.z >> 1, split = blockIdx.z & 1;
    const int n0 = blockIdx.x * BN;
    const int m0 = blockIdx.y * BM;
    const int tid = threadIdx.x, lane = tid & 31, wid = tid >> 5;
    const int warp_m = wid & 1, warp_n = wid >> 1;

    const __half* __restrict__ Ag =
        g_p + ((size_t)b * NQ + m0) * NF + (size_t)split * KPS;
    const __half* __restrict__ Bg =
        g_vt + ((size_t)b * CDIM + n0) * NF + (size_t)split * KPS;

    auto load_stage = [&](int s, int k0) {
        const uint32_t As = sbase + (uint32_t)s * STAGE_BYTES;
        const uint32_t Bs = As + TILE_HALVES * 2;
        #pragma unroll
        for (int j = 0; j < 4; ++j) {
            int flat = tid + 128 * j;
            int row = flat >> 2, k8 = flat & 3;
            cp_async16(As + (uint32_t)(row * LDT + k8 * 8) * 2,
                       Ag + (size_t)row * NF + k0 + k8 * 8);
        }
        #pragma unroll
        for (int j = 0; j < 4; ++j) {
            int flat = tid + 128 * j;
            int row = flat >> 2, k8 = flat & 3;
            cp_async16(Bs + (uint32_t)(row * LDT + k8 * 8) * 2,
                       Bg + (size_t)row * NF + k0 + k8 * 8);
        }
        CP_COMMIT();
    };

    // prologue: 4 stages committed; after wait(2), slots 0 and 1 are landed
    #pragma unroll
    for (int s = 0; s < STAGES - 1; ++s) load_stage(s, s * BK);

    float acc[4][8][4];
    #pragma unroll
    for (int ma = 0; ma < 4; ++ma)
        #pragma unroll
        for (int na = 0; na < 8; ++na)
            #pragma unroll
            for (int r = 0; r < 4; ++r) acc[ma][na][r] = 0.f;

    const int a_row = lane & 15, a_kh = (lane >> 4) << 3;
    const int b_nrow = ((lane >> 4) << 3) + (lane & 7), b_kh = ((lane >> 3) & 1) << 3;

    uint32_t afA[4][4], bfA[8][2], afB[4][4], bfB[8][2];

    CP_WAIT();
    __syncthreads();
    // preload chunk 0, ks-step 0
    LDM_FRAGS(sbase, sbase + TILE_HALVES * 2, 0, afA, bfA);

    for (int c = 0; c < NCH; ++c) {
        // invariant at entry: frags(c, ks0) live in A-buffers;
        // committed groups = STAGES-1 + c  -> wait(2) lands through slot c+1
        CP_WAIT();
        __syncthreads();   // all warps finished iter c-1 (incl. reads of slot c-1)
        if (c + STAGES - 1 < NCH)
            load_stage((c + STAGES - 1) % STAGES, (c + STAGES - 1) * BK);
        else
            CP_COMMIT();   // keep group accounting aligned

        const uint32_t Asc = sbase + (uint32_t)(c % STAGES) * STAGE_BYTES;
        const uint32_t Bsc = Asc + TILE_HALVES * 2;

        LDM_FRAGS(Asc, Bsc, 1, afB, bfB);   // chunk c, ks1 (covered by mma below)
        MMA_ALL(afA, bfA);                  // chunk c, ks0

        if (c + 1 < NCH) {
            const uint32_t Asn = sbase + (uint32_t)((c + 1) % STAGES) * STAGE_BYTES;
            const uint32_t Bsn = Asn + TILE_HALVES * 2;
            LDM_FRAGS(Asn, Bsn, 0, afA, bfA);  // chunk c+1, ks0 (slot landed)
        }
        MMA_ALL(afB, bfB);                  // chunk c, ks1
    }

    const int g = lane >> 2, t = lane & 3;
    float* pout = g_part + ((size_t)(split * NBATCH + b) * NQ + m0) * CDIM + n0;
    #pragma unroll
    for (int ma = 0; ma < 4; ++ma) {
        const int r0 = warp_m * 64 + ma * 16 + g;
        #pragma unroll
        for (int na = 0; na < 8; ++na) {
            const int n = warp_n * 64 + na * 8 + 2 * t;
            *reinterpret_cast<float2*>(pout + (size_t)r0 * CDIM + n) =
                make_float2(acc[ma][na][0], acc[ma][na][1]);
            *reinterpret_cast<float2*>(pout + (size_t)(r0 + 8) * CDIM + n) =
                make_float2(acc[ma][na][2], acc[ma][na][3]);
        }
    }
}

// ---- Kernel 5: combine split-K partials, scale by 1/den ----
__global__ void combine_kernel(float* __restrict__ out) {
    const size_t i = (size_t)blockIdx.x * blockDim.x + threadIdx.x;
    const size_t total4 = (size_t)NBATCH * NQ * CDIM / 4;
    if (i >= total4) return;
    const size_t rowi = i / (CDIM / 4);
    float4 p0 = reinterpret_cast<const float4*>(g_part)[i];
    float4 p1 = reinterpret_cast<const float4*>(g_part)[i + total4];
    const float inv = g_iden[rowi];
    float4 o;
    o.x = (p0.x + p1.x) * inv;
    o.y = (p0.y + p1.y) * inv;
    o.z = (p0.z + p1.z) * inv;
    o.w = (p0.w + p1.w) * inv;
    reinterpret_cast<float4*>(out)[i] = o;
}

extern "C" void kernel_launch(void* const* d_in, const int* in_sizes, int n_in,
                              void* d_out, int out_size) {
    const float* q  = (const float*)d_in[0];
    const float* k  = (const float*)d_in[1];
    const float* v  = (const float*)d_in[2];
    const float* W1 = (const float*)d_in[3];
    const float* b1 = (const float*)d_in[4];
    const float* W2 = (const float*)d_in[5];
    const float* b2 = (const float*)d_in[6];
    float* out = (float*)d_out;

    const int total = NBATCH * (NQ + NF);
    proj_kernel<<<(total + 255) / 256, 256>>>(q, k, W1, b1, W2, b2);

    transpose_v<<<dim3(NF / 32, CDIM / 32, NBATCH), dim3(32, 8)>>>(v);

    exp_kernel<<<dim3(NQ / 8, NBATCH), 256>>>();

    cudaFuncSetAttribute(gemm_kernel, cudaFuncAttributeMaxDynamicSharedMemorySize, GEMM_SMEM);
    gemm_kernel<<<dim3(CDIM / BN, NQ / BM, NBATCH * SPLITK), 128, GEMM_SMEM>>>();

    const int total4 = NBATCH * NQ * CDIM / 4;
    combine_kernel<<<(total4 + 255) / 256, 256>>>(out);
}

// round 15
// speedup vs baseline: 1.1033x; 1.1033x over previous
#include <cuda_runtime.h>
#include <cuda_fp16.h>
#include <cstdint>

#define NBATCH 4
#define NQ 2048
#define NF 16384
#define CDIM 768
#define SCALEF 0.57735026918962576f
#define LN1024 6.9314718055994531f

// ---- GEMM tiling (fp16 operands, fp32 accum), split-K ----
#define BM 128
#define BN 128
#define BK 32
#define SPLITK 2
#define KPS (NF / SPLITK)            // 8192
#define NCH (KPS / BK)               // 256
#define STAGES 4
#define LDT 40                       // padded row length in halves (80B rows)
#define TILE_HALVES (BM * LDT)
#define STAGE_BYTES (2 * TILE_HALVES * 2)
#define GEMM_SMEM (STAGES * STAGE_BYTES)     // 81920

__device__ __align__(16) float4 g_qp[NBATCH * NQ];
__device__ __align__(16) float4 g_kp[NBATCH * NF];
__device__ __align__(16) __half g_p[(size_t)NBATCH * NQ * NF];
__device__ __align__(16) __half g_vt[(size_t)NBATCH * CDIM * NF];
__device__ __align__(16) float g_part[(size_t)SPLITK * NBATCH * NQ * CDIM];
__device__ float g_iden[NBATCH * NQ];
__device__ int g_maxk[NBATCH * 4];   // componentwise max of kp (float as int, >=0)

__device__ __forceinline__ uint32_t smem_u32(const void* p) {
    uint32_t a;
    asm("{ .reg .u64 t; cvta.to.shared.u64 t, %1; cvt.u32.u64 %0, t; }" : "=r"(a) : "l"(p));
    return a;
}
__device__ __forceinline__ void cp_async16(uint32_t saddr, const void* gaddr) {
    asm volatile("cp.async.cg.shared.global [%0], [%1], 16;" :: "r"(saddr), "l"(gaddr));
}
#define CP_COMMIT() asm volatile("cp.async.commit_group;" ::: "memory")
#define CP_WAIT()   asm volatile("cp.async.wait_group %0;" :: "n"(STAGES - 2) : "memory")

__device__ __forceinline__ void ldm_x4(uint32_t& r0, uint32_t& r1, uint32_t& r2,
                                       uint32_t& r3, uint32_t a) {
    asm volatile("ldmatrix.sync.aligned.m8n8.x4.shared.b16 {%0,%1,%2,%3}, [%4];"
                 : "=r"(r0), "=r"(r1), "=r"(r2), "=r"(r3) : "r"(a));
}
__device__ __forceinline__ void mma_f16(float* d, const uint32_t* a, const uint32_t* b) {
    asm volatile(
        "mma.sync.aligned.m16n8k16.row.col.f32.f16.f16.f32 "
        "{%0,%1,%2,%3}, {%4,%5,%6,%7}, {%8,%9}, {%0,%1,%2,%3};"
        : "+f"(d[0]), "+f"(d[1]), "+f"(d[2]), "+f"(d[3])
        : "r"(a[0]), "r"(a[1]), "r"(a[2]), "r"(a[3]), "r"(b[0]), "r"(b[1]));
}

// ---- Kernel 1: 3x3 projections + ReLU; also componentwise kp max per batch ----
// (q pre-scaled by 1/sqrt(3); kp >= 0 so float-as-int atomicMax is valid and
//  idempotent across graph replays -> deterministic)
__global__ void proj_kernel(const float* __restrict__ q, const float* __restrict__ k,
                            const float* __restrict__ W1, const float* __restrict__ b1,
                            const float* __restrict__ W2, const float* __restrict__ b2) {
    int i = blockIdx.x * blockDim.x + threadIdx.x;
    const int nq = NBATCH * NQ, nf = NBATCH * NF;
    if (i < nq) {
        float x0 = q[3 * i], x1 = q[3 * i + 1], x2 = q[3 * i + 2];
        float4 o;
        o.x = SCALEF * fmaxf(0.f, fmaf(W1[0], x0, fmaf(W1[1], x1, fmaf(W1[2], x2, b1[0]))));
        o.y = SCALEF * fmaxf(0.f, fmaf(W1[3], x0, fmaf(W1[4], x1, fmaf(W1[5], x2, b1[1]))));
        o.z = SCALEF * fmaxf(0.f, fmaf(W1[6], x0, fmaf(W1[7], x1, fmaf(W1[8], x2, b1[2]))));
        o.w = 0.f;
        g_qp[i] = o;
    } else if (i < nq + nf) {
        int j = i - nq;
        float x0 = k[3 * j], x1 = k[3 * j + 1], x2 = k[3 * j + 2];
        float4 o;
        o.x = fmaxf(0.f, fmaf(W2[0], x0, fmaf(W2[1], x1, fmaf(W2[2], x2, b2[0]))));
        o.y = fmaxf(0.f, fmaf(W2[3], x0, fmaf(W2[4], x1, fmaf(W2[5], x2, b2[1]))));
        o.z = fmaxf(0.f, fmaf(W2[6], x0, fmaf(W2[7], x1, fmaf(W2[8], x2, b2[2]))));
        o.w = 0.f;
        g_kp[j] = o;
        // warp-reduced componentwise max (whole warp is same batch: NF % 32 == 0)
        float m0 = o.x, m1 = o.y, m2 = o.z;
        #pragma unroll
        for (int d = 16; d > 0; d >>= 1) {
            m0 = fmaxf(m0, __shfl_xor_sync(0xffffffffu, m0, d));
            m1 = fmaxf(m1, __shfl_xor_sync(0xffffffffu, m1, d));
            m2 = fmaxf(m2, __shfl_xor_sync(0xffffffffu, m2, d));
        }
        if ((threadIdx.x & 31) == 0) {
            const int b = j / NF;
            atomicMax(&g_maxk[b * 4 + 0], __float_as_int(m0));
            atomicMax(&g_maxk[b * 4 + 1], __float_as_int(m1));
            atomicMax(&g_maxk[b * 4 + 2], __float_as_int(m2));
        }
    }
}

// ---- Kernel 2: single pass: E = exp(s - qp.maxk + ln1024) fp16, 1/den fp32 ----
// m_r = qp_r . maxk >= true row max (all components nonneg) -> e <= 1024.
// The 2^10 factor cancels exactly in num/den. Softmax shift-exact.
__global__ void __launch_bounds__(256) exp_kernel() {
    const int m0 = blockIdx.x * 8, b = blockIdx.y;
    const int tid = threadIdx.x;
    const float mk0 = __int_as_float(g_maxk[b * 4 + 0]);
    const float mk1 = __int_as_float(g_maxk[b * 4 + 1]);
    const float mk2 = __int_as_float(g_maxk[b * 4 + 2]);
    float4 qv[8];
    float sh[8];
    #pragma unroll
    for (int r = 0; r < 8; ++r) {
        qv[r] = g_qp[b * NQ + m0 + r];
        sh[r] = qv[r].x * mk0 + qv[r].y * mk1 + qv[r].z * mk2 - LN1024;
    }
    const float4* __restrict__ kp = g_kp + b * NF;
    __half* __restrict__ pbase = g_p + ((size_t)b * NQ + m0) * NF;

    float part[8];
    #pragma unroll
    for (int r = 0; r < 8; ++r) part[r] = 0.f;

    for (int i = 2 * tid; i < NF; i += 512) {
        float4 kva = kp[i], kvb = kp[i + 1];
        #pragma unroll
        for (int r = 0; r < 8; ++r) {
            float ea = __expf(qv[r].x * kva.x + qv[r].y * kva.y + qv[r].z * kva.z - sh[r]);
            float eb = __expf(qv[r].x * kvb.x + qv[r].y * kvb.y + qv[r].z * kvb.z - sh[r]);
            part[r] += ea + eb;
            *reinterpret_cast<__half2*>(pbase + (size_t)r * NF + i) =
                __floats2half2_rn(ea, eb);
        }
    }

    __shared__ float red[8][256];
    #pragma unroll
    for (int r = 0; r < 8; ++r) red[r][tid] = part[r];
    __syncthreads();
    #pragma unroll
    for (int s = 128; s > 0; s >>= 1) {
        if (tid < s) {
            #pragma unroll
            for (int r = 0; r < 8; ++r) red[r][tid] += red[r][tid + s];
        }
        __syncthreads();
    }
    if (tid < 8) g_iden[b * NQ + m0 + tid] = 1.f / red[tid][0];
}

// ---- Kernel 3: V transpose to [b][c][k], fp16, half2 stores ----
__global__ void transpose_v(const float* __restrict__ v) {
    __shared__ float tile[32][33];
    const int b = blockIdx.z, k0 = blockIdx.x << 5, c0 = blockIdx.y << 5;
    const int x = threadIdx.x, y = threadIdx.y;
    const float* vb = v + ((size_t)b * NF + k0) * CDIM + c0;
    #pragma unroll
    for (int j = 0; j < 32; j += 8) tile[y + j][x] = vb[(size_t)(y + j) * CDIM + x];
    __syncthreads();
    const int flat = y * 32 + x;
    const int cl = flat >> 4, k2 = (flat & 15) * 2;
    __half* o = g_vt + ((size_t)b * CDIM + c0) * NF + k0;
    #pragma unroll
    for (int p = 0; p < 2; ++p) {
        const int c = cl + p * 16;
        *reinterpret_cast<__half2*>(o + (size_t)c * NF + k2) =
            __floats2half2_rn(tile[k2][c], tile[k2 + 1][c]);
    }
}

// ---- Kernel 4: fp16 mma GEMM (exact R10 structure: best measured 562us) ----
// Grid (6, 16, NBATCH*SPLITK). 128 threads, warp tile 64x64.
__global__ void __launch_bounds__(128, 2) gemm_kernel() {
    extern __shared__ __half sm[];
    const uint32_t sbase = smem_u32(sm);
    const int b = blockIdx.z >> 1, split = blockIdx.z & 1;
    const int n0 = blockIdx.x * BN;
    const int m0 = blockIdx.y * BM;
    const int tid = threadIdx.x, lane = tid & 31, wid = tid >> 5;
    const int warp_m = wid & 1, warp_n = wid >> 1;

    const __half* __restrict__ Ag =
        g_p + ((size_t)b * NQ + m0) * NF + (size_t)split * KPS;
    const __half* __restrict__ Bg =
        g_vt + ((size_t)b * CDIM + n0) * NF + (size_t)split * KPS;

    auto load_stage = [&](int s, int k0) {
        const uint32_t As = sbase + (uint32_t)s * STAGE_BYTES;
        const uint32_t Bs = As + TILE_HALVES * 2;
        #pragma unroll
        for (int j = 0; j < 4; ++j) {
            int flat = tid + 128 * j;
            int row = flat >> 2, k8 = flat & 3;
            cp_async16(As + (uint32_t)(row * LDT + k8 * 8) * 2,
                       Ag + (size_t)row * NF + k0 + k8 * 8);
        }
        #pragma unroll
        for (int j = 0; j < 4; ++j) {
            int flat = tid + 128 * j;
            int row = flat >> 2, k8 = flat & 3;
            cp_async16(Bs + (uint32_t)(row * LDT + k8 * 8) * 2,
                       Bg + (size_t)row * NF + k0 + k8 * 8);
        }
        CP_COMMIT();
    };

    #pragma unroll
    for (int s = 0; s < STAGES - 1; ++s) load_stage(s, s * BK);

    float acc[4][8][4];
    #pragma unroll
    for (int ma = 0; ma < 4; ++ma)
        #pragma unroll
        for (int na = 0; na < 8; ++na)
            #pragma unroll
            for (int r = 0; r < 4; ++r) acc[ma][na][r] = 0.f;

    const int a_row = lane & 15, a_kh = (lane >> 4) << 3;
    const int b_nrow = ((lane >> 4) << 3) + (lane & 7), b_kh = ((lane >> 3) & 1) << 3;

    for (int c = 0; c < NCH; ++c) {
        CP_WAIT();
        __syncthreads();
        if (c + STAGES - 1 < NCH)
            load_stage((c + STAGES - 1) % STAGES, (c + STAGES - 1) * BK);
        else
            CP_COMMIT();

        const int s = c % STAGES;
        const uint32_t As = sbase + (uint32_t)s * STAGE_BYTES;
        const uint32_t Bs = As + TILE_HALVES * 2;

        #pragma unroll
        for (int ks = 0; ks < BK / 16; ++ks) {
            uint32_t af[4][4], bf[8][2];
            #pragma unroll
            for (int ma = 0; ma < 4; ++ma)
                ldm_x4(af[ma][0], af[ma][1], af[ma][2], af[ma][3],
                       As + (uint32_t)((warp_m * 64 + ma * 16 + a_row) * LDT +
                                       ks * 16 + a_kh) * 2);
            #pragma unroll
            for (int n8 = 0; n8 < 4; ++n8)
                ldm_x4(bf[2 * n8][0], bf[2 * n8][1], bf[2 * n8 + 1][0], bf[2 * n8 + 1][1],
                       Bs + (uint32_t)((warp_n * 64 + n8 * 16 + b_nrow) * LDT +
                                       ks * 16 + b_kh) * 2);
            #pragma unroll
            for (int ma = 0; ma < 4; ++ma)
                #pragma unroll
                for (int na = 0; na < 8; ++na)
                    mma_f16(acc[ma][na], af[ma], bf[na]);
        }
    }

    const int g = lane >> 2, t = lane & 3;
    float* pout = g_part + ((size_t)(split * NBATCH + b) * NQ + m0) * CDIM + n0;
    #pragma unroll
    for (int ma = 0; ma < 4; ++ma) {
        const int r0 = warp_m * 64 + ma * 16 + g;
        #pragma unroll
        for (int na = 0; na < 8; ++na) {
            const int n = warp_n * 64 + na * 8 + 2 * t;
            *reinterpret_cast<float2*>(pout + (size_t)r0 * CDIM + n) =
                make_float2(acc[ma][na][0], acc[ma][na][1]);
            *reinterpret_cast<float2*>(pout + (size_t)(r0 + 8) * CDIM + n) =
                make_float2(acc[ma][na][2], acc[ma][na][3]);
        }
    }
}

// ---- Kernel 5: combine split-K partials, scale by 1/den ----
__global__ void combine_kernel(float* __restrict__ out) {
    const size_t i = (size_t)blockIdx.x * blockDim.x + threadIdx.x;
    const size_t total4 = (size_t)NBATCH * NQ * CDIM / 4;
    if (i >= total4) return;
    const size_t rowi = i / (CDIM / 4);
    float4 p0 = reinterpret_cast<const float4*>(g_part)[i];
    float4 p1 = reinterpret_cast<const float4*>(g_part)[i + total4];
    const float inv = g_iden[rowi];
    float4 o;
    o.x = (p0.x + p1.x) * inv;
    o.y = (p0.y + p1.y) * inv;
    o.z = (p0.z + p1.z) * inv;
    o.w = (p0.w + p1.w) * inv;
    reinterpret_cast<float4*>(out)[i] = o;
}

extern "C" void kernel_launch(void* const* d_in, const int* in_sizes, int n_in,
                              void* d_out, int out_size) {
    const float* q  = (const float*)d_in[0];
    const float* k  = (const float*)d_in[1];
    const float* v  = (const float*)d_in[2];
    const float* W1 = (const float*)d_in[3];
    const float* b1 = (const float*)d_in[4];
    const float* W2 = (const float*)d_in[5];
    const float* b2 = (const float*)d_in[6];
    float* out = (float*)d_out;

    const int total = NBATCH * (NQ + NF);
    proj_kernel<<<(total + 255) / 256, 256>>>(q, k, W1, b1, W2, b2);

    transpose_v<<<dim3(NF / 32, CDIM / 32, NBATCH), dim3(32, 8)>>>(v);

    exp_kernel<<<dim3(NQ / 8, NBATCH), 256>>>();

    cudaFuncSetAttribute(gemm_kernel, cudaFuncAttributeMaxDynamicSharedMemorySize, GEMM_SMEM);
    gemm_kernel<<<dim3(CDIM / BN, NQ / BM, NBATCH * SPLITK), 128, GEMM_SMEM>>>();

    const int total4 = NBATCH * NQ * CDIM / 4;
    combine_kernel<<<(total4 + 255) / 256, 256>>>(out);
}